// round 8
// baseline (speedup 1.0000x reference)
#include <cuda_runtime.h>
#include <math.h>
#include <stdint.h>

#define Bq 4
#define Tq 4096
#define Cq 1024
#define Hq 64

// Scratch (tf32 bits): q,k natural [B,T,H]; v transposed [B,H,T].
__device__ uint32_t g_q[Bq * Tq * Hq];
__device__ uint32_t g_k[Bq * Tq * Hq];
__device__ uint32_t g_vT[Bq * Hq * Tq];

__device__ __forceinline__ uint32_t f2tf(float f) {
    uint32_t r;
    asm("cvt.rna.tf32.f32 %0, %1;" : "=r"(r) : "f"(f));
    return r;
}

__device__ __forceinline__ float ex2(float x) {
    float y;
    asm("ex2.approx.ftz.f32 %0, %1;" : "=f"(y) : "f"(x));
    return y;
}

__device__ __forceinline__ void mma_tf32(float d[4], const uint32_t a[4],
                                         const uint32_t b[2]) {
    asm volatile(
        "mma.sync.aligned.m16n8k8.row.col.f32.tf32.tf32.f32 "
        "{%0,%1,%2,%3}, {%4,%5,%6,%7}, {%8,%9}, {%0,%1,%2,%3};\n"
        : "+f"(d[0]), "+f"(d[1]), "+f"(d[2]), "+f"(d[3])
        : "r"(a[0]), "r"(a[1]), "r"(a[2]), "r"(a[3]), "r"(b[0]), "r"(b[1]));
}

__device__ __forceinline__ void cp16(uint32_t saddr, const void* gptr) {
    asm volatile("cp.async.cg.shared.global [%0], [%1], 16;" ::"r"(saddr),
                 "l"(gptr));
}

__device__ __forceinline__ void cp_commit() {
    asm volatile("cp.async.commit_group;" ::: "memory");
}

template <int N>
__device__ __forceinline__ void cp_wait() {
    asm volatile("cp.async.wait_group %0;" ::"n"(N) : "memory");
}

// ---------------------------------------------------------------------------
// Projection: [16384,1024] @ [1024,192], tf32 mma, 3-stage cp.async pipeline.
// W is consumed as raw fp32 (converted at fragment-load time).
// ---------------------------------------------------------------------------
#define PJ_BM 64
#define PJ_KC 32
#define XP 36
#define WP 200
#define PJ_STAGE_WORDS (PJ_BM * XP + PJ_KC * WP)  // 8704
#define PJ_SMEM_WORDS (3 * PJ_STAGE_WORDS)

__device__ __forceinline__ void pj_issue(uint32_t* stage_base,
                                         const float* __restrict__ x,
                                         const float* __restrict__ Wq,
                                         const float* __restrict__ Wk,
                                         const float* __restrict__ Wv, int row0,
                                         int kc, int tid) {
    uint32_t* Xs = stage_base;
    uint32_t* Ws = stage_base + PJ_BM * XP;
#pragma unroll
    for (int rep = 0; rep < 2; rep++) {
        int idx = tid + rep * 256;
        int m = idx >> 3;
        int q = idx & 7;
        cp16((uint32_t)__cvta_generic_to_shared(&Xs[m * XP + q * 4]),
             &x[(size_t)(row0 + m) * Cq + kc + q * 4]);
    }
#pragma unroll
    for (int rep = 0; rep < 6; rep++) {
        int idx = tid + rep * 256;
        int k = idx / 48;
        int q = idx % 48;
        int n = q * 4;
        const float* W = (n < 64) ? Wq : ((n < 128) ? Wk : Wv);
        cp16((uint32_t)__cvta_generic_to_shared(&Ws[k * WP + q * 4]),
             &W[(size_t)(kc + k) * Hq + (n & 63)]);
    }
    cp_commit();
}

__global__ __launch_bounds__(256) void proj_kernel(const float* __restrict__ x,
                                                   const float* __restrict__ Wq,
                                                   const float* __restrict__ Wk,
                                                   const float* __restrict__ Wv) {
    extern __shared__ uint32_t psm[];

    const int tid = threadIdx.x;
    const int lane = tid & 31;
    const int wid = tid >> 5;
    const int r = lane >> 2;
    const int c = lane & 3;
    const int m_base = (wid & 1) * 32;
    const int n_base = (wid >> 1) * 48;
    const int row0 = blockIdx.x * PJ_BM;

    float acc[2][6][4];
#pragma unroll
    for (int mt = 0; mt < 2; mt++)
#pragma unroll
        for (int nt = 0; nt < 6; nt++)
#pragma unroll
            for (int i = 0; i < 4; i++) acc[mt][nt][i] = 0.f;

    const int NCHUNK = Cq / PJ_KC;  // 32
    pj_issue(psm, x, Wq, Wk, Wv, row0, 0, tid);
    pj_issue(psm + PJ_STAGE_WORDS, x, Wq, Wk, Wv, row0, PJ_KC, tid);

    for (int ci = 0; ci < NCHUNK; ci++) {
        if (ci + 2 < NCHUNK) {
            pj_issue(psm + ((ci + 2) % 3) * PJ_STAGE_WORDS, x, Wq, Wk, Wv, row0,
                     (ci + 2) * PJ_KC, tid);
            cp_wait<2>();
        } else if (ci + 1 < NCHUNK) {
            cp_wait<1>();
        } else {
            cp_wait<0>();
        }
        __syncthreads();

        uint32_t* Xs = psm + (ci % 3) * PJ_STAGE_WORDS;
        const float* Xf = (const float*)Xs;
        const float* Wf = (const float*)(Xs + PJ_BM * XP);

#pragma unroll
        for (int ks = 0; ks < 4; ks++) {
            const int k0 = ks * 8;
            uint32_t a[2][4];
#pragma unroll
            for (int mt = 0; mt < 2; mt++) {
                int mb = m_base + mt * 16;
                a[mt][0] = f2tf(Xf[(mb + r) * XP + k0 + c]);
                a[mt][1] = f2tf(Xf[(mb + r + 8) * XP + k0 + c]);
                a[mt][2] = f2tf(Xf[(mb + r) * XP + k0 + c + 4]);
                a[mt][3] = f2tf(Xf[(mb + r + 8) * XP + k0 + c + 4]);
            }
            uint32_t bf[6][2];
#pragma unroll
            for (int nt = 0; nt < 6; nt++) {
                int nb = n_base + nt * 8 + r;
                bf[nt][0] = f2tf(Wf[(k0 + c) * WP + nb]);
                bf[nt][1] = f2tf(Wf[(k0 + 4 + c) * WP + nb]);
            }
#pragma unroll
            for (int mt = 0; mt < 2; mt++)
#pragma unroll
                for (int nt = 0; nt < 6; nt++) mma_tf32(acc[mt][nt], a[mt], bf[nt]);
        }
        __syncthreads();
    }

#pragma unroll
    for (int mt = 0; mt < 2; mt++) {
#pragma unroll
        for (int nt = 0; nt < 6; nt++) {
#pragma unroll
            for (int i = 0; i < 4; i++) {
                int row = row0 + m_base + mt * 16 + r + ((i >= 2) ? 8 : 0);
                int n = n_base + nt * 8 + 2 * c + (i & 1);
                uint32_t val = f2tf(acc[mt][nt][i]);
                if (n < 64) {
                    g_q[row * Hq + n] = val;
                } else if (n < 128) {
                    g_k[row * Hq + (n - 64)] = val;
                } else {
                    int b = row >> 12;
                    int t = row & 4095;
                    g_vT[(b * Hq + (n - 128)) * Tq + t] = val;
                }
            }
        }
    }
}

// ---------------------------------------------------------------------------
// Flash attention: 2-way intra-block key split, double-buffered K, register
// C->A fragment conversion (no P smem).
// ---------------------------------------------------------------------------
#define AT_PAD 68
#define SCALE2 0.04508422002f  // log2(e)/sqrt(1024)
// per group: 2x K(64*68) + V(64*68) = 13056 words; 2 groups
#define AT_GRP_WORDS (3 * 64 * AT_PAD)
#define AT_SMEM_WORDS (2 * AT_GRP_WORDS)

__global__ __launch_bounds__(256, 2) void attn_kernel(float* __restrict__ out) {
    extern __shared__ uint32_t sm[];

    const int tid = threadIdx.x;
    const int lane = tid & 31;
    const int w = tid >> 5;
    const int g = w >> 2;
    const int rg = w & 3;
    const int gtid = tid & 127;
    const int r = lane >> 2;
    const int c = lane & 3;
    const int b = blockIdx.y;
    const int it = (gridDim.x - 1) - blockIdx.x;
    const int qm0 = it * 64;
    const int wr0 = qm0 + rg * 16;

    uint32_t* Kbuf0 = sm + g * AT_GRP_WORDS;
    uint32_t* Kbuf1 = Kbuf0 + 64 * AT_PAD;
    uint32_t* Vg = Kbuf1 + 64 * AT_PAD;
    const int barid = g + 1;

    uint32_t qa[8][4];
    {
        const uint32_t* qb = g_q + (size_t)(b * Tq + wr0) * Hq;
#pragma unroll
        for (int k8 = 0; k8 < 8; k8++) {
            int k0 = k8 * 8;
            qa[k8][0] = qb[r * Hq + k0 + c];
            qa[k8][1] = qb[(r + 8) * Hq + k0 + c];
            qa[k8][2] = qb[r * Hq + k0 + c + 4];
            qa[k8][3] = qb[(r + 8) * Hq + k0 + c + 4];
        }
    }

    float m0 = -1e30f, m1 = -1e30f, l0 = 0.f, l1 = 0.f;
    float o[8][4];
#pragma unroll
    for (int ht = 0; ht < 8; ht++)
#pragma unroll
        for (int i = 0; i < 4; i++) o[ht][i] = 0.f;

    // Prologue: issue K[g] and V[g]
    {
        const int kn0 = g * 64;
        for (int idx = gtid; idx < 1024; idx += 128) {
            int j = idx >> 4;
            int q = idx & 15;
            cp16((uint32_t)__cvta_generic_to_shared(&Kbuf0[j * AT_PAD + q * 4]),
                 &g_k[(size_t)(b * Tq + kn0 + j) * Hq + q * 4]);
        }
        cp_commit();
        for (int idx = gtid; idx < 1024; idx += 128) {
            int h = idx >> 4;
            int q = idx & 15;
            cp16((uint32_t)__cvta_generic_to_shared(&Vg[h * AT_PAD + q * 4]),
                 &g_vT[(size_t)(b * Hq + h) * Tq + kn0 + q * 4]);
        }
        cp_commit();
    }

    for (int kt = g; kt <= it; kt += 2) {
        uint32_t* Kg = ((kt >> 1) & 1) ? Kbuf1 : Kbuf0;
        // Prefetch K[kt+2] into the other K buffer (its last reader finished
        // before the end-of-iteration barrier of iter kt-2).
        if (kt + 2 <= it) {
            uint32_t* Kn = ((kt >> 1) & 1) ? Kbuf0 : Kbuf1;
            const int kn2 = (kt + 2) * 64;
            for (int idx = gtid; idx < 1024; idx += 128) {
                int j = idx >> 4;
                int q = idx & 15;
                cp16((uint32_t)__cvta_generic_to_shared(&Kn[j * AT_PAD + q * 4]),
                     &g_k[(size_t)(b * Tq + kn2 + j) * Hq + q * 4]);
            }
            cp_commit();
            cp_wait<1>();  // retires K[kt] and V[kt]
        } else {
            cp_wait<0>();
        }
        asm volatile("bar.sync %0, %1;" ::"r"(barid), "r"(128) : "memory");

        // S = Q @ K^T
        float s[8][4];
#pragma unroll
        for (int jt = 0; jt < 8; jt++)
#pragma unroll
            for (int i = 0; i < 4; i++) s[jt][i] = 0.f;
#pragma unroll
        for (int k8 = 0; k8 < 8; k8++) {
            const int k0 = k8 * 8;
#pragma unroll
            for (int jt = 0; jt < 8; jt++) {
                uint32_t bf[2];
                bf[0] = Kg[(jt * 8 + r) * AT_PAD + k0 + c];
                bf[1] = Kg[(jt * 8 + r) * AT_PAD + k0 + 4 + c];
                mma_tf32(s[jt], qa[k8], bf);
            }
        }

        const bool diag = (kt == it);
#pragma unroll
        for (int jt = 0; jt < 8; jt++) {
#pragma unroll
            for (int i = 0; i < 4; i++) {
                float v = s[jt][i] * SCALE2;
                if (diag) {
                    int col = jt * 8 + 2 * c + (i & 1);
                    int row = rg * 16 + r + ((i >= 2) ? 8 : 0);
                    if (col > row) v = -1e30f;
                }
                s[jt][i] = v;
            }
        }

        // online softmax (base-2)
        float mx0 = -1e30f, mx1 = -1e30f;
#pragma unroll
        for (int jt = 0; jt < 8; jt++) {
            mx0 = fmaxf(mx0, fmaxf(s[jt][0], s[jt][1]));
            mx1 = fmaxf(mx1, fmaxf(s[jt][2], s[jt][3]));
        }
        mx0 = fmaxf(mx0, __shfl_xor_sync(0xffffffffu, mx0, 1));
        mx0 = fmaxf(mx0, __shfl_xor_sync(0xffffffffu, mx0, 2));
        mx1 = fmaxf(mx1, __shfl_xor_sync(0xffffffffu, mx1, 1));
        mx1 = fmaxf(mx1, __shfl_xor_sync(0xffffffffu, mx1, 2));
        float mn0 = fmaxf(m0, mx0), mn1 = fmaxf(m1, mx1);
        float sum0 = 0.f, sum1 = 0.f;
#pragma unroll
        for (int jt = 0; jt < 8; jt++) {
            s[jt][0] = ex2(s[jt][0] - mn0);
            s[jt][1] = ex2(s[jt][1] - mn0);
            s[jt][2] = ex2(s[jt][2] - mn1);
            s[jt][3] = ex2(s[jt][3] - mn1);
            sum0 += s[jt][0] + s[jt][1];
            sum1 += s[jt][2] + s[jt][3];
        }
        sum0 += __shfl_xor_sync(0xffffffffu, sum0, 1);
        sum0 += __shfl_xor_sync(0xffffffffu, sum0, 2);
        sum1 += __shfl_xor_sync(0xffffffffu, sum1, 1);
        sum1 += __shfl_xor_sync(0xffffffffu, sum1, 2);
        float rs0 = ex2(m0 - mn0), rs1 = ex2(m1 - mn1);
        m0 = mn0;
        m1 = mn1;
        l0 = l0 * rs0 + sum0;
        l1 = l1 * rs1 + sum1;

        // Register C->A fragment conversion for P (same bits as the old smem
        // round-trip). Col j of block jt lives in lane (r, j>>1), slot j&1.
        uint32_t pr[8][4];
        const int srcA = (lane & 28) | (c >> 1);
        const int srcB = srcA + 2;
        const bool odd = (c & 1);
#pragma unroll
        for (int jt = 0; jt < 8; jt++) {
            uint32_t p0 = f2tf(s[jt][0]);
            uint32_t p1 = f2tf(s[jt][1]);
            uint32_t p2 = f2tf(s[jt][2]);
            uint32_t p3 = f2tf(s[jt][3]);
            uint32_t a0A = __shfl_sync(0xffffffffu, p0, srcA);
            uint32_t a1A = __shfl_sync(0xffffffffu, p1, srcA);
            uint32_t a2A = __shfl_sync(0xffffffffu, p2, srcA);
            uint32_t a3A = __shfl_sync(0xffffffffu, p3, srcA);
            uint32_t a0B = __shfl_sync(0xffffffffu, p0, srcB);
            uint32_t a1B = __shfl_sync(0xffffffffu, p1, srcB);
            uint32_t a2B = __shfl_sync(0xffffffffu, p2, srcB);
            uint32_t a3B = __shfl_sync(0xffffffffu, p3, srcB);
            pr[jt][0] = odd ? a1A : a0A;  // P[r][c]
            pr[jt][1] = odd ? a3A : a2A;  // P[r+8][c]
            pr[jt][2] = odd ? a1B : a0B;  // P[r][c+4]
            pr[jt][3] = odd ? a3B : a2B;  // P[r+8][c+4]
        }

#pragma unroll
        for (int ht = 0; ht < 8; ht++) {
            o[ht][0] *= rs0;
            o[ht][1] *= rs0;
            o[ht][2] *= rs1;
            o[ht][3] *= rs1;
        }

        // O += P @ V (V[kt] retired by the same wait as K[kt])
#pragma unroll
        for (int j8 = 0; j8 < 8; j8++) {
            const int j0 = j8 * 8;
#pragma unroll
            for (int ht = 0; ht < 8; ht++) {
                uint32_t bf[2];
                bf[0] = Vg[(ht * 8 + r) * AT_PAD + j0 + c];
                bf[1] = Vg[(ht * 8 + r) * AT_PAD + j0 + 4 + c];
                mma_tf32(o[ht], pr[j8], bf);
            }
        }

        // PV done -> safe to overwrite V with the next tile
        asm volatile("bar.sync %0, %1;" ::"r"(barid), "r"(128) : "memory");
        if (kt + 2 <= it) {
            const int kn2 = (kt + 2) * 64;
            for (int idx = gtid; idx < 1024; idx += 128) {
                int h = idx >> 4;
                int q = idx & 15;
                cp16((uint32_t)__cvta_generic_to_shared(&Vg[h * AT_PAD + q * 4]),
                     &g_vT[(size_t)(b * Hq + h) * Tq + kn2 + q * 4]);
            }
            cp_commit();
        }
    }

    // ------- merge the two key-split states -------
    __syncthreads();
    float* oS = (float*)sm;                   // [4][32][32]
    float* mlS = (float*)(sm + 4 * 32 * 32);  // [4][32][4]
    if (g == 1) {
        float* dst = &oS[(rg * 32 + lane) * 32];
#pragma unroll
        for (int ht = 0; ht < 8; ht++)
#pragma unroll
            for (int i = 0; i < 4; i++) dst[ht * 4 + i] = o[ht][i];
        float* ml = &mlS[(rg * 32 + lane) * 4];
        ml[0] = m0;
        ml[1] = l0;
        ml[2] = m1;
        ml[3] = l1;
    }
    __syncthreads();
    if (g == 0) {
        const float* ml = &mlS[(rg * 32 + lane) * 4];
        float pm0 = ml[0], pl0 = ml[1], pm1 = ml[2], pl1 = ml[3];
        float M0 = fmaxf(m0, pm0), M1 = fmaxf(m1, pm1);
        float a0 = ex2(m0 - M0), b0v = ex2(pm0 - M0);
        float a1 = ex2(m1 - M1), b1v = ex2(pm1 - M1);
        float inv0 = 1.f / (l0 * a0 + pl0 * b0v);
        float inv1 = 1.f / (l1 * a1 + pl1 * b1v);
        const float* po = &oS[(rg * 32 + lane) * 32];
        float* ob0 = out + (size_t)(b * Tq + wr0 + r) * Hq;
        float* ob1 = out + (size_t)(b * Tq + wr0 + r + 8) * Hq;
#pragma unroll
        for (int ht = 0; ht < 8; ht++) {
            int col = ht * 8 + 2 * c;
            float v0 = (o[ht][0] * a0 + po[ht * 4 + 0] * b0v) * inv0;
            float v1 = (o[ht][1] * a0 + po[ht * 4 + 1] * b0v) * inv0;
            float v2 = (o[ht][2] * a1 + po[ht * 4 + 2] * b1v) * inv1;
            float v3 = (o[ht][3] * a1 + po[ht * 4 + 3] * b1v) * inv1;
            *(float2*)&ob0[col] = make_float2(v0, v1);
            *(float2*)&ob1[col] = make_float2(v2, v3);
        }
    }
}

// ---------------------------------------------------------------------------
extern "C" void kernel_launch(void* const* d_in, const int* in_sizes, int n_in,
                              void* d_out, int out_size) {
    const float* x = (const float*)d_in[0];
    const float* Wq = (const float*)d_in[1];
    const float* Wk = (const float*)d_in[2];
    const float* Wv = (const float*)d_in[3];
    float* out = (float*)d_out;

    const size_t pj_smem = PJ_SMEM_WORDS * sizeof(uint32_t);
    cudaFuncSetAttribute(proj_kernel, cudaFuncAttributeMaxDynamicSharedMemorySize,
                         (int)pj_smem);
    proj_kernel<<<(Bq * Tq) / PJ_BM, 256, pj_smem>>>(x, Wq, Wk, Wv);

    const size_t at_smem = AT_SMEM_WORDS * sizeof(uint32_t);
    cudaFuncSetAttribute(attn_kernel, cudaFuncAttributeMaxDynamicSharedMemorySize,
                         (int)at_smem);
    attn_kernel<<<dim3(Tq / 64, Bq), 256, at_smem>>>(out);
}